// round 8
// baseline (speedup 1.0000x reference)
#include <cuda_runtime.h>
#include <cuda_bf16.h>

#define NN   256
#define BB   8
#define SS   14
#define BS   (BB*SS)
#define NDAT 12   // S - len(PILOTS)

// ---------------------------------------------------------------------------
// Fused kernel, single-wave geometry.
// Grid = BS*8 = 896 blocks of 128 threads, 7 blocks/SM -> 1036 slots >= 896,
// so ALL blocks run in one wave (no straggler tail).
// Block = one (b,s) x 32 rows; 4 warps x 8 rows each, 2-deep ring prefetch,
// deferred 8-way interleaved shuffle reduction.
// Phase 1: 256-pt DFT (radix-16 x radix-16) + conj(zc), overlapped with the
// prologue cov loads.
// ---------------------------------------------------------------------------
__global__ void __launch_bounds__(128, 7)
fused_kernel(const float* __restrict__ xr,
             const float* __restrict__ xi,
             const float* __restrict__ cr,
             const float* __restrict__ ci,
             const float* __restrict__ zr,
             const float* __restrict__ zi,
             const int*   __restrict__ shift,
             const int*   __restrict__ gidx,
             float*       __restrict__ out)
{
    __shared__ float2 xs[16 * 17];   // x transposed [n0][n1], padded
    __shared__ float2 aa[17 * 16];   // stage-A output [n0][k0], padded
    __shared__ float  hre_s[264];    // h real, addr = (m&7)*33 + (m>>3)
    __shared__ float  him_s[264];    // h imag, same layout (conflict-free reads)
    __shared__ float2 w16[16];

    const int blk     = blockIdx.x;
    const int bs      = blk >> 3;
    const int rowBase = (blk & 7) * 32;
    const int b       = bs / SS;
    const int s       = bs % SS;
    const int tid     = threadIdx.x;
    const int w       = tid >> 5;
    const int lane    = tid & 31;

    // ---- resolve cov index early; issue prologue loads before the DFT ----
    const int g   = __ldg(&gidx[s]);
    const int idx = (g == 0) ? 0 : __ldg(&shift[b * NDAT + g - 1]);
    const size_t  base = (size_t)idx * NN * NN;
    const float4* cr4  = (const float4*)(cr + base);
    const float4* ci4  = (const float4*)(ci + base);

    const int rw = rowBase + w * 8;      // first of this warp's 8 rows

    float4 A[2][2], C[2][2];             // 2-deep ring, one row per stage
#pragma unroll
    for (int p = 0; p < 2; p++) {
        const size_t ro = (size_t)(rw + p) * 64 + lane * 2;
        A[p][0] = cr4[ro];  A[p][1] = cr4[ro + 1];
        C[p][0] = ci4[ro];  C[p][1] = ci4[ro + 1];
    }

    // ---- phase 1: DFT (overlaps prologue load latency) ----
#pragma unroll
    for (int i = tid; i < NN; i += 128)
        xs[(i & 15) * 17 + (i >> 4)] = make_float2(xr[bs * NN + i],
                                                   xi[bs * NN + i]);
    if (tid < 16) {
        float sn, cs;
        sincospif(-(float)tid * 0.125f, &sn, &cs);   // e^{-2pi i t/16}
        w16[tid] = make_float2(cs, sn);
    }
    __syncthreads();

    // stage A: A'[k0][n0] = (sum_n1 x[16n1+n0] W16^{k0 n1}) * W256^{k0 n0}
#pragma unroll
    for (int h2 = 0; h2 < 2; h2++) {
        const int i  = tid + h2 * 128;
        const int k0 = i >> 4, n0 = i & 15;
        float ar = 0.0f, ai = 0.0f;
#pragma unroll
        for (int n1 = 0; n1 < 16; n1++) {
            const float2 v  = xs[n0 * 17 + n1];
            const float2 ww = w16[(k0 * n1) & 15];
            ar = fmaf(v.x, ww.x, fmaf(-v.y, ww.y, ar));
            ai = fmaf(v.x, ww.y, fmaf( v.y, ww.x, ai));
        }
        float sn, cs;
        sincospif(-(float)(k0 * n0) * (1.0f / 128.0f), &sn, &cs);
        aa[n0 * 17 + k0] = make_float2(ar * cs - ai * sn, ar * sn + ai * cs);
    }
    __syncthreads();

    // stage B: X[16k1+k0] = sum_n0 A'[k0][n0] W16^{k1 n0}; then * conj(zc)
#pragma unroll
    for (int h2 = 0; h2 < 2; h2++) {
        const int i  = tid + h2 * 128;
        const int k0 = i & 15, k1 = i >> 4;
        float Xr = 0.0f, Xi = 0.0f;
#pragma unroll
        for (int n0 = 0; n0 < 16; n0++) {
            const float2 v  = aa[n0 * 17 + k0];
            const float2 ww = w16[(k1 * n0) & 15];
            Xr = fmaf(v.x, ww.x, fmaf(-v.y, ww.y, Xr));
            Xi = fmaf(v.x, ww.y, fmaf( v.y, ww.x, Xi));
        }
        const float a  = zr[i];
        const float bq = -zi[i];
        const int   ad = (i & 7) * 33 + (i >> 3);
        hre_s[ad] = Xr * a - Xi * bq;
        him_s[ad] = Xr * bq + Xi * a;
    }
    __syncthreads();

    // h chunk for this lane: m = lane*8 + j  ->  addr j*33 + lane (bank-clean)
    float hre[8], him[8];
#pragma unroll
    for (int j = 0; j < 8; j++) {
        hre[j] = hre_s[j * 33 + lane];
        him[j] = him_s[j * 33 + lane];
    }

    // ---- phase 2: 8 rows per warp, ring prefetch, deferred reductions ----
    float acc[8];
#pragma unroll
    for (int r = 0; r < 8; r++) {
        const int cur = r & 1;
        float v = 0.0f;
        v = fmaf(A[cur][0].x, hre[0], fmaf(-C[cur][0].x, him[0], v));
        v = fmaf(A[cur][0].y, hre[1], fmaf(-C[cur][0].y, him[1], v));
        v = fmaf(A[cur][0].z, hre[2], fmaf(-C[cur][0].z, him[2], v));
        v = fmaf(A[cur][0].w, hre[3], fmaf(-C[cur][0].w, him[3], v));
        v = fmaf(A[cur][1].x, hre[4], fmaf(-C[cur][1].x, him[4], v));
        v = fmaf(A[cur][1].y, hre[5], fmaf(-C[cur][1].y, him[5], v));
        v = fmaf(A[cur][1].z, hre[6], fmaf(-C[cur][1].z, him[6], v));
        v = fmaf(A[cur][1].w, hre[7], fmaf(-C[cur][1].w, him[7], v));
        acc[r] = v;

        if (r < 6) {   // refill this ring stage with row r+2
            const size_t ro = (size_t)(rw + r + 2) * 64 + lane * 2;
            A[cur][0] = cr4[ro];  A[cur][1] = cr4[ro + 1];
            C[cur][0] = ci4[ro];  C[cur][1] = ci4[ro + 1];
        }
    }

    // 8 independent shuffle-reduce chains, interleaved (latency-hidden)
#pragma unroll
    for (int o = 16; o > 0; o >>= 1) {
#pragma unroll
        for (int r = 0; r < 8; r++)
            acc[r] += __shfl_xor_sync(0xffffffffu, acc[r], o);
    }

    if (lane == 0) {
        float4* o4 = (float4*)(out + bs * NN + rw);
        o4[0] = make_float4(acc[0], acc[1], acc[2], acc[3]);
        o4[1] = make_float4(acc[4], acc[5], acc[6], acc[7]);
    }
}

extern "C" void kernel_launch(void* const* d_in, const int* in_sizes, int n_in,
                              void* d_out, int out_size)
{
    const float* xr    = (const float*)d_in[0];
    const float* xi    = (const float*)d_in[1];
    const float* cr    = (const float*)d_in[2];
    const float* ci    = (const float*)d_in[3];
    const float* zr    = (const float*)d_in[4];
    const float* zi    = (const float*)d_in[5];
    const int*   shift = (const int*)d_in[6];
    const int*   gidx  = (const int*)d_in[7];

    fused_kernel<<<BS * 8, 128>>>(xr, xi, cr, ci, zr, zi, shift, gidx,
                                  (float*)d_out);
}

// round 10
// speedup vs baseline: 1.2948x; 1.2948x over previous
#include <cuda_runtime.h>
#include <cuda_bf16.h>

#define NN   256
#define BB   8
#define SS   14
#define BS   (BB*SS)
#define NDAT 12   // S - len(PILOTS)

// ---------------------------------------------------------------------------
// Fused streaming kernel (R7 code base; ring depth 2; 4 blocks/SM).
// Grid = BS*4 = 448 blocks x 256 threads; at 4 blocks/SM -> 592 slots -> one
// wave, no straggler tail. Block = one (b,s) x 64 rows = 8 tiles of 8 rows
// (one row per warp per tile), 2-deep ring prefetch.
// Phase 1 (256-pt DFT via radix-16 x radix-16 + conj(zc)) overlaps the
// pipeline fill. Twiddles via sincospif (proven R7 path).
// ---------------------------------------------------------------------------
__global__ void __launch_bounds__(256, 4)
fused_kernel(const float* __restrict__ xr,
             const float* __restrict__ xi,
             const float* __restrict__ cr,
             const float* __restrict__ ci,
             const float* __restrict__ zr,
             const float* __restrict__ zi,
             const int*   __restrict__ shift,
             const int*   __restrict__ gidx,
             float*       __restrict__ out)
{
    __shared__ float2 xs[16 * 17];   // x transposed [n0][n1], padded
    __shared__ float2 aa[17 * 16];   // stage-A output [n0][k0], padded
    __shared__ float2 hs[NN];
    __shared__ float2 w16[16];

    const int blk     = blockIdx.x;
    const int bs      = blk >> 2;
    const int rowBase = (blk & 3) * 64;
    const int b       = bs / SS;
    const int s       = bs % SS;
    const int tid     = threadIdx.x;
    const int w       = tid >> 5;
    const int lane    = tid & 31;

    // ---- resolve cov index early so prologue loads issue before the DFT ----
    const int g   = __ldg(&gidx[s]);
    const int idx = (g == 0) ? 0 : __ldg(&shift[b * NDAT + g - 1]);
    const size_t  base = (size_t)idx * NN * NN;
    const float4* cr4  = (const float4*)(cr + base);
    const float4* ci4  = (const float4*)(ci + base);

    // 2-stage ring buffers: stage p holds one row (4 float4) per lane
    float4 A[2][2], C[2][2];

    // ---- prologue: issue tiles 0..1 (rows rowBase + t*8 + w) ----
#pragma unroll
    for (int p = 0; p < 2; p++) {
        const size_t ro = (size_t)(rowBase + p * 8 + w) * 64 + lane * 2;
        A[p][0] = cr4[ro];  A[p][1] = cr4[ro + 1];
        C[p][0] = ci4[ro];  C[p][1] = ci4[ro + 1];
    }

    // ---- phase 1: DFT (overlaps the pipeline fill) ----
    {
        float2 xv = make_float2(xr[bs * NN + tid], xi[bs * NN + tid]);
        xs[(tid & 15) * 17 + (tid >> 4)] = xv;   // xs[n0][n1], n = 16*n1 + n0
        if (tid < 16) {
            float sn, cs;
            sincospif(-(float)tid * 0.125f, &sn, &cs);   // e^{-2pi i t/16}
            w16[tid] = make_float2(cs, sn);
        }
    }
    __syncthreads();

    {   // stage A: A'[k0][n0] = (sum_n1 x[16n1+n0] W16^{k0 n1}) * W256^{k0 n0}
        const int k0 = tid >> 4, n0 = tid & 15;
        float ar = 0.0f, ai = 0.0f;
#pragma unroll
        for (int n1 = 0; n1 < 16; n1++) {
            const float2 v  = xs[n0 * 17 + n1];
            const float2 ww = w16[(k0 * n1) & 15];
            ar = fmaf(v.x, ww.x, fmaf(-v.y, ww.y, ar));
            ai = fmaf(v.x, ww.y, fmaf( v.y, ww.x, ai));
        }
        float sn, cs;
        sincospif(-(float)(k0 * n0) * (1.0f / 128.0f), &sn, &cs);
        aa[n0 * 17 + k0] = make_float2(ar * cs - ai * sn, ar * sn + ai * cs);
    }
    __syncthreads();

    {   // stage B: X[16k1+k0] = sum_n0 A'[k0][n0] W16^{k1 n0}; then * conj(zc)
        const int k0 = tid & 15, k1 = tid >> 4;
        float Xr = 0.0f, Xi = 0.0f;
#pragma unroll
        for (int n0 = 0; n0 < 16; n0++) {
            const float2 v  = aa[n0 * 17 + k0];
            const float2 ww = w16[(k1 * n0) & 15];
            Xr = fmaf(v.x, ww.x, fmaf(-v.y, ww.y, Xr));
            Xi = fmaf(v.x, ww.y, fmaf( v.y, ww.x, Xi));
        }
        const float a  = zr[tid];
        const float bq = -zi[tid];
        hs[tid] = make_float2(Xr * a - Xi * bq, Xr * bq + Xi * a);
    }
    __syncthreads();

    // h chunk for this lane (m = lane*8 .. lane*8+7)
    float2 h[8];
#pragma unroll
    for (int j = 0; j < 8; j++) h[j] = hs[lane * 8 + j];

    // ---- phase 2: 8-tile streaming loop over the 2-stage ring ----
#pragma unroll
    for (int t = 0; t < 8; t++) {
        const int cur = t & 1;

        float re = 0.0f;
        re = fmaf(A[cur][0].x, h[0].x, fmaf(-C[cur][0].x, h[0].y, re));
        re = fmaf(A[cur][0].y, h[1].x, fmaf(-C[cur][0].y, h[1].y, re));
        re = fmaf(A[cur][0].z, h[2].x, fmaf(-C[cur][0].z, h[2].y, re));
        re = fmaf(A[cur][0].w, h[3].x, fmaf(-C[cur][0].w, h[3].y, re));
        re = fmaf(A[cur][1].x, h[4].x, fmaf(-C[cur][1].x, h[4].y, re));
        re = fmaf(A[cur][1].y, h[5].x, fmaf(-C[cur][1].y, h[5].y, re));
        re = fmaf(A[cur][1].z, h[6].x, fmaf(-C[cur][1].z, h[6].y, re));
        re = fmaf(A[cur][1].w, h[7].x, fmaf(-C[cur][1].w, h[7].y, re));

        // refill this stage with tile t+2 (keeps 1 tile always in flight)
        if (t < 6) {
            const size_t ro = (size_t)(rowBase + (t + 2) * 8 + w) * 64 + lane * 2;
            A[cur][0] = cr4[ro];  A[cur][1] = cr4[ro + 1];
            C[cur][0] = ci4[ro];  C[cur][1] = ci4[ro + 1];
        }

#pragma unroll
        for (int o = 16; o > 0; o >>= 1)
            re += __shfl_xor_sync(0xffffffffu, re, o);

        if (lane == 0) out[bs * NN + rowBase + t * 8 + w] = re;
    }
}

extern "C" void kernel_launch(void* const* d_in, const int* in_sizes, int n_in,
                              void* d_out, int out_size)
{
    const float* xr    = (const float*)d_in[0];
    const float* xi    = (const float*)d_in[1];
    const float* cr    = (const float*)d_in[2];
    const float* ci    = (const float*)d_in[3];
    const float* zr    = (const float*)d_in[4];
    const float* zi    = (const float*)d_in[5];
    const int*   shift = (const int*)d_in[6];
    const int*   gidx  = (const int*)d_in[7];

    fused_kernel<<<BS * 4, 256>>>(xr, xi, cr, ci, zr, zi, shift, gidx,
                                  (float*)d_out);
}